// round 4
// baseline (speedup 1.0000x reference)
#include <cuda_runtime.h>
#include <math.h>

// Hausdorff, D=H=W=20, V=8000, batch 2.
// Exact integer squared-distance separable EDT; sqrt/20 only on final maxima.
// ONE launch, 80 blocks (4 transforms x 20 x-slabs), per-transform software
// barriers (20 arrivals each). All 80 blocks co-resident -> spin is safe.
// z-pass is O(1) per cell via bit tricks; y/x passes use explicit tree-min.

#define VV    8000
#define INF_S 32000   // squared-distance "infinity" (max legit = 3*19^2 = 1083)
#define PAD   8       // 32B padding between contended counters

__device__ int g_F2[4][VV];       // after z+y passes, per transform t = n*2+m
__device__ int g_gmax[4 * PAD];   // slot (n*2+dir)*PAD, value = best_d2 + 1, 0 = none
__device__ int g_any[2 * PAD];    // any(mask A) per sample
__device__ int g_barc[4 * PAD];   // per-transform barrier counters
__device__ int g_done = 0;

__global__ void __launch_bounds__(416, 1)
haus_one(const float* __restrict__ predict,
         const float* __restrict__ targetp,
         float* __restrict__ out)
{
    __shared__ unsigned int rowbits[20];  // z-occupancy bits per y row
    __shared__ short F1[400];
    __shared__ int   sred;

    const int b = blockIdx.x;            // t*20 + x
    const int t = b / 20, x = b - t * 20;
    const int n = t >> 1, m = t & 1;
    const float* setSrc = (m ? targetp : predict) + n * VV + x * 400;
    const float* othSrc = (m ? predict : targetp) + n * VV + x * 400;
    const int tid = threadIdx.x;

    if (tid < 20) rowbits[tid] = 0;
    if (tid == 0) sred = 0;
    __syncthreads();

    // ---- masks (jnp.round == round-half-even == rintf) ----
    int y = 0, z = 0, s = 0, oo = 0;
    if (tid < 400) {
        y = tid / 20; z = tid - y * 20;
        s = (rintf(setSrc[tid]) != 0.0f) ? 1 : 0;
        int o = (rintf(othSrc[tid]) != 0.0f) ? 1 : 0;
        oo = o & (s ^ 1);                        // "other-only" point
        if (s) atomicOr(&rowbits[y], 1u << z);
    }
    // anyA pushed early (m==0 blocks hold mask A); overlaps with barrier latency
    int anyv = __any_sync(0xffffffffu, s);
    if (m == 0 && (tid & 31) == 0 && anyv) atomicOr(&g_any[n * PAD], 1);
    __syncthreads();

    // ---- z-pass: O(1) nearest set bit via clz/ffs ----
    if (tid < 400) {
        unsigned mask = rowbits[y];
        int dist = 100;                           // > 19 == "none"
        unsigned lo = mask & ((2u << z) - 1u);    // bits 0..z
        if (lo) dist = z - (31 - __clz(lo));
        unsigned hi = mask >> z;                  // bits z..19
        if (hi) dist = min(dist, __ffs(hi) - 1);
        F1[tid] = (short)((dist <= 19) ? dist * dist : INF_S);
    }
    __syncthreads();

    // ---- y-pass: 20 candidates, explicit tree-min ----
    if (tid < 400) {
        int c[20];
        #pragma unroll
        for (int yp = 0; yp < 20; yp++) {
            int dy = y - yp;
            c[yp] = (int)F1[yp * 20 + z] + dy * dy;
        }
        #pragma unroll
        for (int st = 1; st < 20; st <<= 1)
            #pragma unroll
            for (int i = 0; i + st < 20; i += (st << 1)) c[i] = min(c[i], c[i + st]);
        g_F2[t][x * 400 + tid] = min(c[0], INF_S);
    }
    __threadfence();           // each writer publishes its own STG
    __syncthreads();

    // ---- per-transform barrier: arrive via atomic, poll via volatile LDG ----
    if (tid == 0) {
        atomicAdd(&g_barc[t * PAD], 1);
        volatile int* vb = (volatile int*)&g_barc[t * PAD];
        while (*vb < 20) { }
        __threadfence();
    }
    __syncthreads();

    // ---- x-pass + classification + reduction ----
    int localMax = 0;                             // encoded best+1; 0 = none
    if (tid < 400) {
        const int* __restrict__ f2 = &g_F2[t][tid];
        int c[20];
        #pragma unroll
        for (int xp = 0; xp < 20; xp++) {
            int dx = x - xp;
            c[xp] = __ldcg(f2 + xp * 400) + dx * dx;
        }
        #pragma unroll
        for (int st = 1; st < 20; st <<= 1)
            #pragma unroll
            for (int i = 0; i + st < 20; i += (st << 1)) c[i] = min(c[i], c[i + st]);
        if (oo) localMax = c[0] + 1;
    }
    localMax = __reduce_max_sync(0xffffffffu, localMax);
    if ((tid & 31) == 0 && localMax > 0) atomicMax(&sred, localMax);
    __syncthreads();

    // ---- tail: one atomicMax per block, last-done block finalizes ----
    if (tid == 0) {
        int dir = 1 - m;   // m==1 (set=B): A-only->B = distA slot 0; m==0: distB slot 1
        if (sred > 0) atomicMax(&g_gmax[(n * 2 + dir) * PAD], sred);
        __threadfence();
        int done = atomicAdd(&g_done, 1);
        if (done == 79) {
            __threadfence();
            volatile int* vmax = (volatile int*)g_gmax;
            volatile int* vany = (volatile int*)g_any;
            float sum = 0.0f;
            #pragma unroll
            for (int nn = 0; nn < 2; nn++) {
                int a2   = vmax[(nn * 2 + 0) * PAD] - 1;
                int b2   = vmax[(nn * 2 + 1) * PAD] - 1;
                int anyA = vany[nn * PAD];
                float dA = 0.0f;
                if (a2 >= 0) dA = (a2 > 1083) ? 1e9f : sqrtf((float)a2) * 0.05f;
                float dB = 0.0f;
                if (b2 >= 0) dB = anyA ? ((b2 > 1083) ? 1e9f : sqrtf((float)b2) * 0.05f)
                                       : 999.0f;
                sum += fmaxf(dA, dB);
                vmax[(nn * 2 + 0) * PAD] = 0;
                vmax[(nn * 2 + 1) * PAD] = 0;
                vany[nn * PAD] = 0;
            }
            out[0] = sum * 0.5f;
            #pragma unroll
            for (int tt = 0; tt < 4; tt++) ((volatile int*)g_barc)[tt * PAD] = 0;
            *(volatile int*)&g_done = 0;
        }
    }
}

extern "C" void kernel_launch(void* const* d_in, const int* in_sizes, int n_in,
                              void* d_out, int out_size)
{
    const float* predict = (const float*)d_in[0];
    const float* targetp = (const float*)d_in[1];
    haus_one<<<80, 416>>>(predict, targetp, (float*)d_out);
}